// round 2
// baseline (speedup 1.0000x reference)
#include <cuda_runtime.h>

// Problem constants (fixed by the reference)
#define NROWS 8192
#define MM    128
#define DZ    128
#define DX    128
#define HH    4

// Scratch: xW[m][:] + b, precomputed once per launch sequence.
__device__ float4 g_xWb[MM];

// ---------------------------------------------------------------------------
// Kernel A: xWb[m][h] = sum_d x[d][m] * W[DZ+d][h] + b[h]
// One block, 128 threads (thread == m). x loads are coalesced across threads;
// W loads are uniform (broadcast). ~128 iterations of 4 FMAs.
// ---------------------------------------------------------------------------
__global__ void xwb_kernel(const float* __restrict__ x,
                           const float* __restrict__ W,
                           const float* __restrict__ b) {
    int m = threadIdx.x;
    float a0 = b[0], a1 = b[1], a2 = b[2], a3 = b[3];
#pragma unroll 8
    for (int d = 0; d < DX; d++) {
        float xv = x[d * MM + m];
        float4 w = *reinterpret_cast<const float4*>(W + (DZ + d) * HH);
        a0 = fmaf(xv, w.x, a0);
        a1 = fmaf(xv, w.y, a1);
        a2 = fmaf(xv, w.z, a2);
        a3 = fmaf(xv, w.w, a3);
    }
    g_xWb[m] = make_float4(a0, a1, a2, a3);
}

// ---------------------------------------------------------------------------
// Kernel B: per row n, compute zW[n][0..3] via a 128-lane reduction, then
// each of 128 threads writes out[n][m=t][0..3] = relu(zW + xWb[t]) as float4.
// 4 rows per block (512 threads) -> 8 KB coalesced store per CTA.
// ---------------------------------------------------------------------------
#define ROWS_PER_BLOCK 4

__global__ __launch_bounds__(128 * ROWS_PER_BLOCK)
void fused_kernel(const float* __restrict__ z,
                  const float* __restrict__ W,
                  float* __restrict__ out) {
    __shared__ float4 sred[ROWS_PER_BLOCK][4];  // per-group, per-warp partials

    int tid  = threadIdx.x;
    int grp  = tid >> 7;          // which row within the block (0..3)
    int t    = tid & 127;         // lane within the 128-thread row group
    int wgrp = t >> 5;            // warp index within group (0..3)
    int lane = t & 31;

    int n = blockIdx.x * ROWS_PER_BLOCK + grp;

    // Per-thread partial products for the 4 heads
    float zv = z[n * DZ + t];
    float4 w = *reinterpret_cast<const float4*>(W + t * HH);  // 16B aligned
    float p0 = zv * w.x;
    float p1 = zv * w.y;
    float p2 = zv * w.z;
    float p3 = zv * w.w;

    // Intra-warp butterfly reduction (lanes of this row group's warp)
#pragma unroll
    for (int off = 16; off > 0; off >>= 1) {
        p0 += __shfl_xor_sync(0xffffffffu, p0, off);
        p1 += __shfl_xor_sync(0xffffffffu, p1, off);
        p2 += __shfl_xor_sync(0xffffffffu, p2, off);
        p3 += __shfl_xor_sync(0xffffffffu, p3, off);
    }
    if (lane == 0) sred[grp][wgrp] = make_float4(p0, p1, p2, p3);
    __syncthreads();

    // Cross-warp combine (4 partials), broadcast-read from shared
    float4 r0 = sred[grp][0];
    float4 r1 = sred[grp][1];
    float4 r2 = sred[grp][2];
    float4 r3 = sred[grp][3];
    float s0 = r0.x + r1.x + r2.x + r3.x;
    float s1 = r0.y + r1.y + r2.y + r3.y;
    float s2 = r0.z + r1.z + r2.z + r3.z;
    float s3 = r0.w + r1.w + r2.w + r3.w;

    // Epilogue: each thread handles m = t
    float4 xw = g_xWb[t];
    float4 o;
    o.x = fmaxf(s0 + xw.x, 0.0f);
    o.y = fmaxf(s1 + xw.y, 0.0f);
    o.z = fmaxf(s2 + xw.z, 0.0f);
    o.w = fmaxf(s3 + xw.w, 0.0f);

    reinterpret_cast<float4*>(out)[n * MM + t] = o;
}

// ---------------------------------------------------------------------------
// Launch. Inputs (metadata order): z [N*DZ], x [DX*M], W [(DZ+DX)*H], b [H].
// Output: float32 [N*M*H].
// ---------------------------------------------------------------------------
extern "C" void kernel_launch(void* const* d_in, const int* in_sizes, int n_in,
                              void* d_out, int out_size) {
    const float* z = (const float*)d_in[0];
    const float* x = (const float*)d_in[1];
    const float* W = (const float*)d_in[2];
    const float* b = (const float*)d_in[3];
    float* out = (float*)d_out;

    xwb_kernel<<<1, MM>>>(x, W, b);
    fused_kernel<<<NROWS / ROWS_PER_BLOCK, 128 * ROWS_PER_BLOCK>>>(z, W, out);
}

// round 5
// speedup vs baseline: 1.0915x; 1.0915x over previous
#include <cuda_runtime.h>

// Problem constants (fixed by the reference)
#define NROWS 8192
#define MM    128
#define DZ    128
#define DX    128
#define HH    4

// Scratch precomputed per launch:
//   g_zWb[n] = z[n,:] @ W[:DZ, :]            (float4, one per row)
//   g_xWb[m] = x[:,m] @ W[DZ:, :] + b        (float4, one per column)
__device__ float4 g_zWb[NROWS];
__device__ float4 g_xWb[MM];

// ---------------------------------------------------------------------------
// Kernel 1: precompute zWb (one warp per row) and xWb (last block).
// Row path: warp loads z[n, lane + 32k] (coalesced, k=0..3), multiplies by
// W rows (L1-resident 2KB), butterfly-reduces 4 head accumulators, lane 0
// stores a float4.
// ---------------------------------------------------------------------------
#define K1_THREADS 256
#define ROWS_PER_BLOCK (K1_THREADS / 32)   // 8 rows per block
#define K1_ROWBLOCKS (NROWS / ROWS_PER_BLOCK)  // 1024

__global__ __launch_bounds__(K1_THREADS)
void precompute_kernel(const float* __restrict__ z,
                       const float* __restrict__ x,
                       const float* __restrict__ W,
                       const float* __restrict__ b) {
    if (blockIdx.x == K1_ROWBLOCKS) {
        // xWb path: 128 threads, thread == m
        int m = threadIdx.x;
        if (m < MM) {
            float a0 = b[0], a1 = b[1], a2 = b[2], a3 = b[3];
#pragma unroll 8
            for (int d = 0; d < DX; d++) {
                float xv = x[d * MM + m];
                float4 w = *reinterpret_cast<const float4*>(W + (DZ + d) * HH);
                a0 = fmaf(xv, w.x, a0);
                a1 = fmaf(xv, w.y, a1);
                a2 = fmaf(xv, w.z, a2);
                a3 = fmaf(xv, w.w, a3);
            }
            g_xWb[m] = make_float4(a0, a1, a2, a3);
        }
        return;
    }

    int warp = threadIdx.x >> 5;
    int lane = threadIdx.x & 31;
    int n = blockIdx.x * ROWS_PER_BLOCK + warp;

    float a0 = 0.f, a1 = 0.f, a2 = 0.f, a3 = 0.f;
#pragma unroll
    for (int k = 0; k < 4; k++) {
        int d = lane + 32 * k;
        float zv = __ldg(z + n * DZ + d);
        float4 w = *reinterpret_cast<const float4*>(W + d * HH);
        a0 = fmaf(zv, w.x, a0);
        a1 = fmaf(zv, w.y, a1);
        a2 = fmaf(zv, w.z, a2);
        a3 = fmaf(zv, w.w, a3);
    }
#pragma unroll
    for (int off = 16; off > 0; off >>= 1) {
        a0 += __shfl_xor_sync(0xffffffffu, a0, off);
        a1 += __shfl_xor_sync(0xffffffffu, a1, off);
        a2 += __shfl_xor_sync(0xffffffffu, a2, off);
        a3 += __shfl_xor_sync(0xffffffffu, a3, off);
    }
    if (lane == 0) g_zWb[n] = make_float4(a0, a1, a2, a3);
}

// ---------------------------------------------------------------------------
// Kernel 2: pure broadcast store. One float4 (= one [n,m,:] vector) per
// thread. zWb[n] is warp-uniform within a 128-span (L1/L2 broadcast);
// xWb is 2KB, L1-resident. No shuffles, no barriers.
// ---------------------------------------------------------------------------
#define K2_THREADS 256
#define K2_BLOCKS ((NROWS * MM) / K2_THREADS)   // 4096

__global__ __launch_bounds__(K2_THREADS)
void store_kernel(float* __restrict__ out) {
    int idx = blockIdx.x * K2_THREADS + threadIdx.x;  // over N*M
    int n = idx >> 7;        // / MM
    int m = idx & (MM - 1);

    float4 zw = g_zWb[n];
    float4 xw = g_xWb[m];
    float4 o;
    o.x = fmaxf(zw.x + xw.x, 0.0f);
    o.y = fmaxf(zw.y + xw.y, 0.0f);
    o.z = fmaxf(zw.z + xw.z, 0.0f);
    o.w = fmaxf(zw.w + xw.w, 0.0f);

    reinterpret_cast<float4*>(out)[idx] = o;
}

// ---------------------------------------------------------------------------
// Launch. Inputs (metadata order): z [N*DZ], x [DX*M], W [(DZ+DX)*H], b [H].
// Output: float32 [N*M*H].
// ---------------------------------------------------------------------------
extern "C" void kernel_launch(void* const* d_in, const int* in_sizes, int n_in,
                              void* d_out, int out_size) {
    const float* z = (const float*)d_in[0];
    const float* x = (const float*)d_in[1];
    const float* W = (const float*)d_in[2];
    const float* b = (const float*)d_in[3];
    float* out = (float*)d_out;

    precompute_kernel<<<K1_ROWBLOCKS + 1, K1_THREADS>>>(z, x, W, b);
    store_kernel<<<K2_BLOCKS, K2_THREADS>>>(out);
}

// round 8
// speedup vs baseline: 1.6140x; 1.4787x over previous
#include <cuda_runtime.h>

// Problem constants (fixed by the reference)
#define NROWS 8192
#define MM    128
#define DZ    128
#define DX    128
#define HH    4

#define THREADS 512
#define ROWS_PER_BLK 32
#define NBLOCKS (NROWS / ROWS_PER_BLK)   // 256

// ---------------------------------------------------------------------------
// Single fused kernel. Block b owns rows [b*32, b*32+32).
//  Phase 1: xWb -> shared (512 threads: m = tid&127, quarter q = tid>>7)
//  Phase 2: zWb for 32 rows -> shared (one row per warp, 2 iters)
//  Phase 3: 8 independent coalesced float4 stores per thread.
// ---------------------------------------------------------------------------
__global__ __launch_bounds__(THREADS)
void fused_all(const float* __restrict__ z,
               const float* __restrict__ x,
               const float* __restrict__ W,
               const float* __restrict__ b,
               float* __restrict__ out) {
    __shared__ float4 s_part[4][MM];       // 8 KB: xWb partials per quarter
    __shared__ float4 s_xw[MM];            // 2 KB: xWb + b
    __shared__ float4 s_zw[ROWS_PER_BLK];  // 512 B: zWb rows

    const int tid  = threadIdx.x;
    const int lane = tid & 31;
    const int warp = tid >> 5;
    const int n_base = blockIdx.x * ROWS_PER_BLK;
    const float4* __restrict__ W4 = reinterpret_cast<const float4*>(W);

    // ---- Phase 1: xWb partial sums (each thread: 32 d's for one m) ----
    {
        const int m = tid & (MM - 1);
        const int q = tid >> 7;              // 0..3
        float a0 = 0.f, a1 = 0.f, a2 = 0.f, a3 = 0.f;
#pragma unroll 8
        for (int j = 0; j < 32; j++) {
            int d = q * 32 + j;
            float xv = x[d * MM + m];
            float4 w = W4[DZ + d];
            a0 = fmaf(xv, w.x, a0);
            a1 = fmaf(xv, w.y, a1);
            a2 = fmaf(xv, w.z, a2);
            a3 = fmaf(xv, w.w, a3);
        }
        s_part[q][m] = make_float4(a0, a1, a2, a3);
    }

    // ---- Phase 2: zWb, one row per warp, 2 iterations ----
#pragma unroll
    for (int it = 0; it < 2; it++) {
        int r = warp + 16 * it;              // 0..31
        int n = n_base + r;
        float4 zv = reinterpret_cast<const float4*>(z + (size_t)n * DZ)[lane];
        float4 w0 = W4[4 * lane + 0];
        float4 w1 = W4[4 * lane + 1];
        float4 w2 = W4[4 * lane + 2];
        float4 w3 = W4[4 * lane + 3];
        float a0 = zv.x * w0.x + zv.y * w1.x + zv.z * w2.x + zv.w * w3.x;
        float a1 = zv.x * w0.y + zv.y * w1.y + zv.z * w2.y + zv.w * w3.y;
        float a2 = zv.x * w0.z + zv.y * w1.z + zv.z * w2.z + zv.w * w3.z;
        float a3 = zv.x * w0.w + zv.y * w1.w + zv.z * w2.w + zv.w * w3.w;
#pragma unroll
        for (int off = 16; off > 0; off >>= 1) {
            a0 += __shfl_xor_sync(0xffffffffu, a0, off);
            a1 += __shfl_xor_sync(0xffffffffu, a1, off);
            a2 += __shfl_xor_sync(0xffffffffu, a2, off);
            a3 += __shfl_xor_sync(0xffffffffu, a3, off);
        }
        if (lane == 0) s_zw[r] = make_float4(a0, a1, a2, a3);
    }

    __syncthreads();

    // ---- Combine xWb partials + bias (first 128 threads) ----
    if (tid < MM) {
        float4 p0 = s_part[0][tid];
        float4 p1 = s_part[1][tid];
        float4 p2 = s_part[2][tid];
        float4 p3 = s_part[3][tid];
        float4 bb = *reinterpret_cast<const float4*>(b);
        s_xw[tid] = make_float4(p0.x + p1.x + p2.x + p3.x + bb.x,
                                p0.y + p1.y + p2.y + p3.y + bb.y,
                                p0.z + p1.z + p2.z + p3.z + bb.z,
                                p0.w + p1.w + p2.w + p3.w + bb.w);
    }

    __syncthreads();

    // ---- Phase 3: 8 independent coalesced float4 stores per thread ----
    float4* __restrict__ out4 = reinterpret_cast<float4*>(out) + (size_t)n_base * MM;
#pragma unroll
    for (int it = 0; it < 8; it++) {
        int idx = it * THREADS + tid;        // 0..4095 over (row, m)
        int nl = idx >> 7;
        int m  = idx & (MM - 1);
        float4 zw = s_zw[nl];
        float4 xw = s_xw[m];
        float4 o;
        o.x = fmaxf(zw.x + xw.x, 0.0f);
        o.y = fmaxf(zw.y + xw.y, 0.0f);
        o.z = fmaxf(zw.z + xw.z, 0.0f);
        o.w = fmaxf(zw.w + xw.w, 0.0f);
        out4[idx] = o;
    }
}

// ---------------------------------------------------------------------------
// Launch. Inputs (metadata order): z [N*DZ], x [DX*M], W [(DZ+DX)*H], b [H].
// Output: float32 [N*M*H].
// ---------------------------------------------------------------------------
extern "C" void kernel_launch(void* const* d_in, const int* in_sizes, int n_in,
                              void* d_out, int out_size) {
    const float* z = (const float*)d_in[0];
    const float* x = (const float*)d_in[1];
    const float* W = (const float*)d_in[2];
    const float* b = (const float*)d_in[3];
    float* out = (float*)d_out;

    fused_all<<<NBLOCKS, THREADS>>>(z, x, W, b, out);
}